// round 16
// baseline (speedup 1.0000x reference)
#include <cuda_runtime.h>
#include <math_constants.h>
#include <cstdint>

// DotAttention: context[b,f] = softmax_t(<hd[b],he[b,t]>) . he[b,t,f]
// b=64, t=2048, f=1024, fp32.
// R15 = R14 partial (3-stage cp.async pipeline, atomics-free epilogue)
// + fused per-batch combine: the last-arriving CTA of each batch combines
// its 8 chunks. Publication via ONE atom.acq_rel.gpu RMW per CTA (thread0)
// instead of R5's per-thread __threadfence (which cost ~1.6us).

#define BB 64
#define TT 2048
#define FF 1024
#define SPLITS 8
#define TCHUNK (TT / SPLITS)             // 256 rows per CTA
#define NWARPS 8
#define ROWS_PER_WARP (TCHUNK / NWARPS)  // 32
#define STAGES 3
#define ROW_BYTES (FF * 4)               // 4096 B per row
#define SMEM_BYTES (NWARPS * STAGES * ROW_BYTES)  // 98304

// scratch (allocation-free)
__device__ float g_ctx[(size_t)BB * SPLITS * FF];   // 2 MB
__device__ float g_m[BB * SPLITS];
__device__ float g_l[BB * SPLITS];
__device__ unsigned int g_cnt[BB];                  // zero-init; reset by last CTA

#define CP_ASYNC16(dst, src) \
    asm volatile("cp.async.cg.shared.global [%0], [%1], 16;" \
                 :: "r"(dst), "l"(src) : "memory")
#define CP_COMMIT() asm volatile("cp.async.commit_group;" ::: "memory")
#define CP_WAIT2()  asm volatile("cp.async.wait_group 2;" ::: "memory")
#define CP_WAIT0()  asm volatile("cp.async.wait_group 0;" ::: "memory")

__device__ __forceinline__ unsigned int smem_u32(const void* p) {
    unsigned int a;
    asm("{ .reg .u64 t; cvta.to.shared.u64 t, %1; cvt.u32.u64 %0, t; }"
        : "=r"(a) : "l"(p));
    return a;
}

__global__ __launch_bounds__(256)
void attn_fused_kernel(const float* __restrict__ hd,
                       const float* __restrict__ he,
                       float* __restrict__ out) {
    extern __shared__ char smem_raw[];   // SMEM_BYTES
    const int s    = blockIdx.x;         // t-split
    const int b    = blockIdx.y;         // batch
    const int warp = threadIdx.x >> 5;
    const int lane = threadIdx.x & 31;

    // per-warp private stage base; lane offset folded in
    const unsigned int sbase = smem_u32(smem_raw)
                             + warp * (STAGES * ROW_BYTES) + lane * 16;

    // q: 32 floats per lane, lane-major so loads are coalesced.
    const float4* q4 = reinterpret_cast<const float4*>(hd + (size_t)b * FF);
    float4 q[8];
#pragma unroll
    for (int j = 0; j < 8; j++) q[j] = q4[j * 32 + lane];

    float  m = -CUDART_INF_F;
    float  l = 0.0f;
    float4 acc[8];
#pragma unroll
    for (int j = 0; j < 8; j++) acc[j] = make_float4(0.f, 0.f, 0.f, 0.f);

    const int t_base = s * TCHUNK + warp;

    // ---- prologue: prefetch rows 0..2 into stages 0..2 ----
#pragma unroll
    for (int st = 0; st < STAGES; st++) {
        const int t = t_base + st * NWARPS;
        const float4* src = reinterpret_cast<const float4*>(
            he + ((size_t)b * TT + t) * FF);
        const unsigned int dst = sbase + st * ROW_BYTES;
#pragma unroll
        for (int j = 0; j < 8; j++)
            CP_ASYNC16(dst + j * 512, src + j * 32 + lane);
        CP_COMMIT();
    }

    int stage = 0;
    for (int r = 0; r < ROWS_PER_WARP; r++) {
        if (r >= ROWS_PER_WARP - STAGES) { CP_WAIT0(); } else { CP_WAIT2(); }

        const unsigned int stg = sbase + stage * ROW_BYTES;

        // row into registers from smem (conflict-free LDS.128)
        float4 v[8];
#pragma unroll
        for (int j = 0; j < 8; j++) {
            asm volatile("ld.shared.v4.f32 {%0,%1,%2,%3}, [%4];"
                         : "=f"(v[j].x), "=f"(v[j].y),
                           "=f"(v[j].z), "=f"(v[j].w)
                         : "r"(stg + j * 512));
        }

        // prefetch row r+STAGES into the just-consumed stage, BEFORE compute
        if (r + STAGES < ROWS_PER_WARP) {
            const int t2 = t_base + (r + STAGES) * NWARPS;
            const float4* src = reinterpret_cast<const float4*>(
                he + ((size_t)b * TT + t2) * FF);
#pragma unroll
            for (int j = 0; j < 8; j++)
                CP_ASYNC16(stg + j * 512, src + j * 32 + lane);
            CP_COMMIT();
        }

        // dot(q, v): 4 independent accumulator chains
        float d0 = 0.f, d1 = 0.f, d2 = 0.f, d3 = 0.f;
#pragma unroll
        for (int j = 0; j < 8; j++) {
            d0 += v[j].x * q[j].x;
            d1 += v[j].y * q[j].y;
            d2 += v[j].z * q[j].z;
            d3 += v[j].w * q[j].w;
        }
        float d = (d0 + d1) + (d2 + d3);
#pragma unroll
        for (int off = 16; off; off >>= 1)
            d += __shfl_xor_sync(0xffffffffu, d, off);
        // d is warp-uniform -> uniform branch below (no divergence)

        if (d <= m) {
            const float p = __expf(d - m);
            l += p;
#pragma unroll
            for (int j = 0; j < 8; j++) {
                acc[j].x += p * v[j].x;
                acc[j].y += p * v[j].y;
                acc[j].z += p * v[j].z;
                acc[j].w += p * v[j].w;
            }
        } else {
            const float sc = __expf(m - d);   // 0 on first row (m = -inf)
            m = d;
            l = l * sc + 1.0f;                // p = exp(d - d) = 1
#pragma unroll
            for (int j = 0; j < 8; j++) {
                acc[j].x = acc[j].x * sc + v[j].x;
                acc[j].y = acc[j].y * sc + v[j].y;
                acc[j].z = acc[j].z * sc + v[j].z;
                acc[j].w = acc[j].w * sc + v[j].w;
            }
        }

        stage = (stage + 1 == STAGES) ? 0 : stage + 1;
    }

    // ---- combine the 8 warps of this CTA (no atomics) ----
    __shared__ float s_m[NWARPS];
    __shared__ float s_l[NWARPS];
    __shared__ unsigned int s_last;
    // reuse dead stage smem: 8 rows x 1024 floats = 32KB
    float* s_red = reinterpret_cast<float*>(smem_raw);

    if (lane == 0) { s_m[warp] = m; s_l[warp] = l; }
    __syncthreads();   // stages dead; s_m/s_l visible

    float M = s_m[0];
#pragma unroll
    for (int w = 1; w < NWARPS; w++) M = fmaxf(M, s_m[w]);

    // each warp stores its rescaled accumulator row (conflict-free STS.128)
    const float sc = __expf(m - M);
    float4* myrow = reinterpret_cast<float4*>(s_red + warp * FF);
#pragma unroll
    for (int j = 0; j < 8; j++) {
        float4 a = acc[j];
        a.x *= sc; a.y *= sc; a.z *= sc; a.w *= sc;
        myrow[j * 32 + lane] = a;
    }
    __syncthreads();

    const int chunk = b * SPLITS + s;
    if (threadIdx.x == 0) {
        float L = 0.0f;
#pragma unroll
        for (int w = 0; w < NWARPS; w++) L += s_l[w] * __expf(s_m[w] - M);
        g_m[chunk] = M;
        g_l[chunk] = L;
    }

    // tree-reduce: each thread owns one float4 column slice (tid = 0..255)
    {
        const int i = threadIdx.x;            // float4 index 0..255
        const float4* r4 = reinterpret_cast<const float4*>(s_red);
        float4 sum = r4[i];                   // warp 0 row
#pragma unroll
        for (int w = 1; w < NWARPS; w++) {
            float4 a = r4[w * (FF / 4) + i];
            sum.x += a.x; sum.y += a.y; sum.z += a.z; sum.w += a.w;
        }
        reinterpret_cast<float4*>(g_ctx + (size_t)chunk * FF)[i] = sum;
    }

    // ---- last-arriving CTA of this batch combines its 8 chunks ----
    __syncthreads();   // all g_ctx/g_m/g_l stores of this CTA done
    if (threadIdx.x == 0) {
        unsigned int old;
        // release: publish this CTA's writes; acquire: see other CTAs' writes
        asm volatile("atom.acq_rel.gpu.global.add.u32 %0, [%1], 1;"
                     : "=r"(old) : "l"(&g_cnt[b]) : "memory");
        s_last = (old == SPLITS - 1);
        if (old == SPLITS - 1) g_cnt[b] = 0;   // reset for next graph replay
    }
    __syncthreads();
    if (!s_last) return;

    // combine: 256 threads, one float4 of output each
    float mv[SPLITS], lv[SPLITS];
#pragma unroll
    for (int c = 0; c < SPLITS; c++) {
        mv[c] = __ldcg(&g_m[b * SPLITS + c]);
        lv[c] = __ldcg(&g_l[b * SPLITS + c]);
    }
    float Mb = mv[0];
#pragma unroll
    for (int c = 1; c < SPLITS; c++) Mb = fmaxf(Mb, mv[c]);

    float e[SPLITS];
    float Lb = 0.0f;
#pragma unroll
    for (int c = 0; c < SPLITS; c++) {
        e[c] = __expf(mv[c] - Mb);
        Lb += lv[c] * e[c];
    }
    const float invL = 1.0f / Lb;

    const int i = threadIdx.x;   // float4 index 0..255
    float4 r = make_float4(0.f, 0.f, 0.f, 0.f);
#pragma unroll
    for (int c = 0; c < SPLITS; c++) {
        const float4 a = __ldcg(reinterpret_cast<const float4*>(
            g_ctx + ((size_t)b * SPLITS + c) * FF) + i);
        r.x += a.x * e[c];
        r.y += a.y * e[c];
        r.z += a.z * e[c];
        r.w += a.w * e[c];
    }
    r.x *= invL; r.y *= invL; r.z *= invL; r.w *= invL;
    reinterpret_cast<float4*>(out + (size_t)b * FF)[i] = r;
}

extern "C" void kernel_launch(void* const* d_in, const int* in_sizes, int n_in,
                              void* d_out, int out_size) {
    const float* hd = (const float*)d_in[0];   // (64, 1024)
    const float* he = (const float*)d_in[1];   // (64, 2048, 1024)
    float* out = (float*)d_out;                // (64, 1024)
    (void)in_sizes; (void)n_in; (void)out_size;

    static int attr_set = 0;
    if (!attr_set) {
        cudaFuncSetAttribute(attn_fused_kernel,
                             cudaFuncAttributeMaxDynamicSharedMemorySize,
                             SMEM_BYTES);
        attr_set = 1;
    }

    dim3 grid(SPLITS, BB);
    attn_fused_kernel<<<grid, 256, SMEM_BYTES>>>(hd, he, out);
}